// round 7
// baseline (speedup 1.0000x reference)
#include <cuda_runtime.h>
#include <cuda_bf16.h>

#define BOX 256
#define KS 9
#define PNT 20000
#define NB 16
#define NN 32
#define NL 3
#define LAT 8

// Shared-memory layout offsets (floats). All float4-read regions 16B aligned.
#define S_W1   0        // linamp1_W   [32*4]        = 128
#define S_AW   128      // ampblock_W  [3*1024]      = 3072
#define S_AB   3200     // ampblock_b  [96]
#define S_W2   3296     // linamp2_W   [32]
#define S_L0   3328     // lin0_W padded [32][12]    = 384
#define S_DW   3712     // deform_W    [3072]
#define S_DB   6784     // deform_b    [96]
#define S_A1   6880     // lin1a_W     [96]
#define S_B1   6976     // lin1b_W     [9]
#define S_KP   6992     // k2pad [4][9][12]          = 432   (6992*4 % 16 == 0)
#define S_TOT  7424

__device__ __forceinline__ void red_add_v4(float* addr, float a, float b,
                                           float c, float d) {
    asm volatile("red.global.add.v4.f32 [%0], {%1, %2, %3, %4};"
                 :: "l"(addr), "f"(a), "f"(b), "f"(c), "f"(d) : "memory");
}

__global__ __launch_bounds__(128, 2) void decoder_kernel(
    const float* __restrict__ z,          // [16,8]
    const float* __restrict__ r,          // [16,3,3]
    const float* __restrict__ pos,        // [20000,3]
    const float* __restrict__ amp,        // [1]
    const float* __restrict__ linamp1_W,  // [32,4]
    const float* __restrict__ ampblock_W, // [3,32,32]
    const float* __restrict__ ampblock_b, // [3,32]
    const float* __restrict__ linamp2_W,  // [1,32]
    const float* __restrict__ linamp2_b,  // [1]
    const float* __restrict__ lin0_W,     // [32,10]
    const float* __restrict__ deform_W,   // [3,32,32]
    const float* __restrict__ deform_b,   // [3,32]
    const float* __restrict__ lin1a_W,    // [3,32]
    const float* __restrict__ lin1b_W,    // [3,3]
    const float* __restrict__ k2,         // [9,9]
    float* __restrict__ out_img,          // [16,256,256]
    float* __restrict__ out_posdef,       // [16,20000,3]
    float* __restrict__ out_res,          // [16,20000,3]
    float* __restrict__ out_ampc,         // [16,20000]
    int write_extras)
{
    __shared__ float s[S_TOT];
    const int t = threadIdx.x;

    // Cooperative weight staging (128 threads)
    for (int i = t; i < 128;  i += 128) s[S_W1 + i] = linamp1_W[i];
    for (int i = t; i < 3072; i += 128) s[S_AW + i] = ampblock_W[i];
    for (int i = t; i < 96;   i += 128) s[S_AB + i] = ampblock_b[i];
    for (int i = t; i < 32;   i += 128) s[S_W2 + i] = linamp2_W[i];
    // lin0_W padded from [32][10] to [32][12]
    for (int i = t; i < 384; i += 128) {
        const int row = i / 12;
        const int c   = i - row * 12;
        s[S_L0 + i] = (c < 10) ? lin0_W[row * 10 + c] : 0.0f;
    }
    for (int i = t; i < 3072; i += 128) s[S_DW + i] = deform_W[i];
    for (int i = t; i < 96;   i += 128) s[S_DB + i] = deform_b[i];
    for (int i = t; i < 96;   i += 128) s[S_A1 + i] = lin1a_W[i];
    for (int i = t; i < 9;    i += 128) s[S_B1 + i] = lin1b_W[i];
    // Shifted zero-padded kernel table: k2pad[off][row][12]
    for (int i = t; i < 432; i += 128) {
        const int o   = i / 108;
        const int rem = i - o * 108;
        const int row = rem / 12;
        const int m   = rem - row * 12;
        const int j   = m - o;
        s[S_KP + i] = (j >= 0 && j < KS) ? k2[row * KS + j] : 0.0f;
    }
    __syncthreads();

    // Each thread handles two points of the SAME batch: (b, p) and (b, p+10000)
    const int tid = blockIdx.x * 128 + t;
    if (tid >= NB * (PNT / 2)) return;
    const int b  = tid / (PNT / 2);
    const int p  = tid - b * (PNT / 2);
    const int p0 = p;
    const int p1 = p + PNT / 2;
    const int idx0 = b * PNT + p0;
    const int idx1 = b * PNT + p1;

    const float px0 = pos[p0 * 3 + 0], py0 = pos[p0 * 3 + 1], pz0 = pos[p0 * 3 + 2];
    const float px1 = pos[p1 * 3 + 0], py1 = pos[p1 * 3 + 1], pz1 = pos[p1 * 3 + 2];

    float x0[NN], x1[NN];
    float y0[NN], y1[NN];
    float amp_corr0, amp_corr1;

    // ---------------- amplitude head (both points) ----------------
    {
        const float cz = z[b * LAT + (LAT - 1)];
        #pragma unroll
        for (int j = 0; j < NN; j++) {
            const float4 w = *reinterpret_cast<const float4*>(&s[S_W1 + j * 4]);
            x0[j] = fmaf(w.x, px0, fmaf(w.y, py0, fmaf(w.z, pz0, w.w * cz)));
            x1[j] = fmaf(w.x, px1, fmaf(w.y, py1, fmaf(w.z, pz1, w.w * cz)));
        }
        #pragma unroll
        for (int l = 0; l < NL; l++) {
            #pragma unroll
            for (int j = 0; j < NN; j++) {
                const float4* wr = reinterpret_cast<const float4*>(&s[S_AW + l * 1024 + j * 32]);
                const float bias = s[S_AB + l * 32 + j];
                float a0 = bias, a1 = bias;
                #pragma unroll
                for (int i = 0; i < 8; i++) {
                    const float4 w = wr[i];
                    a0 = fmaf(w.x, x0[4 * i + 0], a0);
                    a1 = fmaf(w.x, x1[4 * i + 0], a1);
                    a0 = fmaf(w.y, x0[4 * i + 1], a0);
                    a1 = fmaf(w.y, x1[4 * i + 1], a1);
                    a0 = fmaf(w.z, x0[4 * i + 2], a0);
                    a1 = fmaf(w.z, x1[4 * i + 2], a1);
                    a0 = fmaf(w.w, x0[4 * i + 3], a0);
                    a1 = fmaf(w.w, x1[4 * i + 3], a1);
                }
                y0[j] = fmaxf(a0, 0.0f) + x0[j];
                y1[j] = fmaxf(a1, 0.0f) + x1[j];
            }
            #pragma unroll
            for (int j = 0; j < NN; j++) { x0[j] = y0[j]; x1[j] = y1[j]; }
        }
        const float b2 = linamp2_b[0];
        float s0 = b2, s1 = b2;
        #pragma unroll
        for (int i = 0; i < 8; i++) {
            const float4 w = *reinterpret_cast<const float4*>(&s[S_W2 + i * 4]);
            s0 = fmaf(w.x, x0[4 * i + 0], s0);
            s1 = fmaf(w.x, x1[4 * i + 0], s1);
            s0 = fmaf(w.y, x0[4 * i + 1], s0);
            s1 = fmaf(w.y, x1[4 * i + 1], s1);
            s0 = fmaf(w.z, x0[4 * i + 2], s0);
            s1 = fmaf(w.z, x1[4 * i + 2], s1);
            s0 = fmaf(w.w, x0[4 * i + 3], s0);
            s1 = fmaf(w.w, x1[4 * i + 3], s1);
        }
        amp_corr0 = 1.0f / (1.0f + expf(-s0));
        amp_corr1 = 1.0f / (1.0f + expf(-s1));
    }

    // ---------------- deformation head (both points) ----------------
    float in0[12], in1[12];
    in0[0] = px0; in0[1] = py0; in0[2] = pz0;
    in1[0] = px1; in1[1] = py1; in1[2] = pz1;
    #pragma unroll
    for (int i = 0; i < LAT - 1; i++) {
        const float zi = z[b * LAT + i];
        in0[3 + i] = zi;
        in1[3 + i] = zi;
    }
    in0[10] = 0.0f; in0[11] = 0.0f;
    in1[10] = 0.0f; in1[11] = 0.0f;

    #pragma unroll
    for (int j = 0; j < NN; j++) {
        const float4* wr = reinterpret_cast<const float4*>(&s[S_L0 + j * 12]);
        float a0 = 0.0f, a1 = 0.0f;
        #pragma unroll
        for (int i = 0; i < 3; i++) {
            const float4 w = wr[i];
            a0 = fmaf(w.x, in0[4 * i + 0], a0);
            a1 = fmaf(w.x, in1[4 * i + 0], a1);
            a0 = fmaf(w.y, in0[4 * i + 1], a0);
            a1 = fmaf(w.y, in1[4 * i + 1], a1);
            a0 = fmaf(w.z, in0[4 * i + 2], a0);
            a1 = fmaf(w.z, in1[4 * i + 2], a1);
            a0 = fmaf(w.w, in0[4 * i + 3], a0);
            a1 = fmaf(w.w, in1[4 * i + 3], a1);
        }
        x0[j] = a0;
        x1[j] = a1;
    }
    #pragma unroll
    for (int l = 0; l < NL; l++) {
        #pragma unroll
        for (int j = 0; j < NN; j++) {
            const float4* wr = reinterpret_cast<const float4*>(&s[S_DW + l * 1024 + j * 32]);
            const float bias = s[S_DB + l * 32 + j];
            float a0 = bias, a1 = bias;
            #pragma unroll
            for (int i = 0; i < 8; i++) {
                const float4 w = wr[i];
                a0 = fmaf(w.x, x0[4 * i + 0], a0);
                a1 = fmaf(w.x, x1[4 * i + 0], a1);
                a0 = fmaf(w.y, x0[4 * i + 1], a0);
                a1 = fmaf(w.y, x1[4 * i + 1], a1);
                a0 = fmaf(w.z, x0[4 * i + 2], a0);
                a1 = fmaf(w.z, x1[4 * i + 2], a1);
                a0 = fmaf(w.w, x0[4 * i + 3], a0);
                a1 = fmaf(w.w, x1[4 * i + 3], a1);
            }
            y0[j] = fmaxf(a0, 0.0f) + x0[j];
            y1[j] = fmaxf(a1, 0.0f) + x1[j];
        }
        #pragma unroll
        for (int j = 0; j < NN; j++) { x0[j] = y0[j]; x1[j] = y1[j]; }
    }
    float tv0[3], tv1[3];
    #pragma unroll
    for (int k = 0; k < 3; k++) {
        const float4* wr = reinterpret_cast<const float4*>(&s[S_A1 + k * 32]);
        float a0 = 0.0f, a1 = 0.0f;
        #pragma unroll
        for (int i = 0; i < 8; i++) {
            const float4 w = wr[i];
            a0 = fmaf(w.x, x0[4 * i + 0], a0);
            a1 = fmaf(w.x, x1[4 * i + 0], a1);
            a0 = fmaf(w.y, x0[4 * i + 1], a0);
            a1 = fmaf(w.y, x1[4 * i + 1], a1);
            a0 = fmaf(w.z, x0[4 * i + 2], a0);
            a1 = fmaf(w.z, x1[4 * i + 2], a1);
            a0 = fmaf(w.w, x0[4 * i + 3], a0);
            a1 = fmaf(w.w, x1[4 * i + 3], a1);
        }
        tv0[k] = tanhf(a0);
        tv1[k] = tanhf(a1);
    }
    float res0[3], res1[3];
    #pragma unroll
    for (int k = 0; k < 3; k++) {
        const float w0 = s[S_B1 + k * 3 + 0];
        const float w1 = s[S_B1 + k * 3 + 1];
        const float w2 = s[S_B1 + k * 3 + 2];
        res0[k] = fmaf(w0, tv0[0], fmaf(w1, tv0[1], w2 * tv0[2]));
        res1[k] = fmaf(w0, tv1[0], fmaf(w1, tv1[1], w2 * tv1[2]));
    }
    const float pdx0 = px0 + res0[0], pdy0 = py0 + res0[1], pdz0 = pz0 + res0[2];
    const float pdx1 = px1 + res1[0], pdy1 = py1 + res1[1], pdz1 = pz1 + res1[2];

    // ---------------- outputs (non-image) ----------------
    if (write_extras) {
        out_posdef[idx0 * 3 + 0] = pdx0;
        out_posdef[idx0 * 3 + 1] = pdy0;
        out_posdef[idx0 * 3 + 2] = pdz0;
        out_posdef[idx1 * 3 + 0] = pdx1;
        out_posdef[idx1 * 3 + 1] = pdy1;
        out_posdef[idx1 * 3 + 2] = pdz1;
        out_res[idx0 * 3 + 0] = res0[0];
        out_res[idx0 * 3 + 1] = res0[1];
        out_res[idx0 * 3 + 2] = res0[2];
        out_res[idx1 * 3 + 0] = res1[0];
        out_res[idx1 * 3 + 1] = res1[1];
        out_res[idx1 * 3 + 2] = res1[2];
        out_ampc[idx0] = amp_corr0;
        out_ampc[idx1] = amp_corr1;
    }

    // ---------------- project + splat (both points) ----------------
    const float* rb = &r[b * 9];
    const float r00 = rb[0], r01 = rb[1], r02 = rb[2];
    const float r10 = rb[3], r11 = rb[4], r12 = rb[5];
    const float ampv = amp[0];
    float* img = out_img + (size_t)b * BOX * BOX;

    #pragma unroll
    for (int u = 0; u < 2; u++) {
        const float pdx = u ? pdx1 : pdx0;
        const float pdy = u ? pdy1 : pdy0;
        const float pdz = u ? pdz1 : pdz0;
        const float ac  = u ? amp_corr1 : amp_corr0;

        const float proj0 = fmaf(r00, pdx, fmaf(r01, pdy, r02 * pdz));
        const float proj1 = fmaf(r10, pdx, fmaf(r11, pdy, r12 * pdz));
        const float amps = ampv * ac;
        const int cx = __float2int_rn((proj0 + 0.5f) * (float)(BOX - 1));
        const int cy = __float2int_rn((proj1 + 0.5f) * (float)(BOX - 1));

        const int bx  = (cx - 4) & ~3;
        const int off = (cx - 4) - bx;
        const bool v0 = (bx >= 0) && (bx < BOX);
        const bool v1 = (bx + 4 >= 0) && (bx + 4 < BOX);
        const bool v2 = (bx + 8 >= 0) && (bx + 8 < BOX);
        const float* kp = &s[S_KP + off * 108];

        #pragma unroll
        for (int i = 0; i < KS; i++) {
            const int yy = cy + i - KS / 2;
            if ((unsigned)yy < (unsigned)BOX) {
                const float4 w0 = *reinterpret_cast<const float4*>(kp + i * 12 + 0);
                const float4 w1 = *reinterpret_cast<const float4*>(kp + i * 12 + 4);
                const float4 w2 = *reinterpret_cast<const float4*>(kp + i * 12 + 8);
                float* row = img + yy * BOX;
                if (v0) red_add_v4(row + bx,
                                   amps * w0.x, amps * w0.y, amps * w0.z, amps * w0.w);
                if (v1) red_add_v4(row + bx + 4,
                                   amps * w1.x, amps * w1.y, amps * w1.z, amps * w1.w);
                if (v2) red_add_v4(row + bx + 8,
                                   amps * w2.x, amps * w2.y, amps * w2.z, amps * w2.w);
            }
        }
    }
}

extern "C" void kernel_launch(void* const* d_in, const int* in_sizes, int n_in,
                              void* d_out, int out_size) {
    const float* z          = (const float*)d_in[0];
    const float* r          = (const float*)d_in[1];
    const float* pos        = (const float*)d_in[2];
    const float* amp        = (const float*)d_in[3];
    const float* linamp1_W  = (const float*)d_in[4];
    const float* ampblock_W = (const float*)d_in[5];
    const float* ampblock_b = (const float*)d_in[6];
    const float* linamp2_W  = (const float*)d_in[7];
    const float* linamp2_b  = (const float*)d_in[8];
    const float* lin0_W     = (const float*)d_in[9];
    const float* deform_W   = (const float*)d_in[10];
    const float* deform_b   = (const float*)d_in[11];
    const float* lin1a_W    = (const float*)d_in[12];
    const float* lin1b_W    = (const float*)d_in[13];
    const float* k2         = (const float*)d_in[14];
    // d_in[15] = d (always 1 for this problem)

    float* out = (float*)d_out;
    const long long IMG = (long long)NB * BOX * BOX;          // 1,048,576
    const long long PD  = (long long)NB * PNT * 3;            //   960,000
    const int write_extras = (out_size >= (int)(IMG + 2 * PD + (long long)NB * PNT)) ? 1 : 0;

    // Zero the image accumulation region (graph-capturable async memset)
    cudaMemsetAsync(out, 0, (size_t)IMG * sizeof(float));

    float* out_img    = out;
    float* out_posdef = out + IMG;
    float* out_res    = out + IMG + PD;
    float* out_ampc   = out + IMG + 2 * PD;

    const int total = NB * (PNT / 2);   // 160000 threads, 2 points each
    const int threads = 128;
    const int blocks = (total + threads - 1) / threads;
    decoder_kernel<<<blocks, threads>>>(
        z, r, pos, amp, linamp1_W, ampblock_W, ampblock_b, linamp2_W,
        linamp2_b, lin0_W, deform_W, deform_b, lin1a_W, lin1b_W, k2,
        out_img, out_posdef, out_res, out_ampc, write_extras);
}

// round 9
// speedup vs baseline: 1.3399x; 1.3399x over previous
#include <cuda_runtime.h>
#include <cuda_bf16.h>

#define BOX 256
#define KS 9
#define PNT 20000
#define NB 16
#define NN 32
#define NL 3
#define LAT 8

// Scratch for amp_corr between the two kernels (device global: allowed)
__device__ float g_ampc[NB * PNT];

__device__ __forceinline__ void red_add_v4(float* addr, float a, float b,
                                           float c, float d) {
    asm volatile("red.global.add.v4.f32 [%0], {%1, %2, %3, %4};"
                 :: "l"(addr), "f"(a), "f"(b), "f"(c), "f"(d) : "memory");
}

// ===================== Kernel 1: amplitude head =====================
// smem: W1 [128], AW [3072], AB [96], W2 [32]  -> 3328 floats
#define K1_W1 0
#define K1_AW 128
#define K1_AB 3200
#define K1_W2 3296
#define K1_TOT 3328

__global__ __launch_bounds__(128) void amp_kernel(
    const float* __restrict__ z,          // [16,8]
    const float* __restrict__ pos,        // [20000,3]
    const float* __restrict__ linamp1_W,  // [32,4]
    const float* __restrict__ ampblock_W, // [3,32,32]
    const float* __restrict__ ampblock_b, // [3,32]
    const float* __restrict__ linamp2_W,  // [1,32]
    const float* __restrict__ linamp2_b,  // [1]
    float* __restrict__ out_ampc,         // [16,20000] or null-equivalent
    int write_extras)
{
    __shared__ float s[K1_TOT];
    const int t = threadIdx.x;
    for (int i = t; i < 128;  i += 128) s[K1_W1 + i] = linamp1_W[i];
    for (int i = t; i < 3072; i += 128) s[K1_AW + i] = ampblock_W[i];
    for (int i = t; i < 96;   i += 128) s[K1_AB + i] = ampblock_b[i];
    for (int i = t; i < 32;   i += 128) s[K1_W2 + i] = linamp2_W[i];
    __syncthreads();

    const int idx = blockIdx.x * 128 + t;
    if (idx >= NB * PNT) return;
    const int b = idx / PNT;
    const int p = idx - b * PNT;

    const float px = pos[p * 3 + 0];
    const float py = pos[p * 3 + 1];
    const float pz = pos[p * 3 + 2];
    const float cz = z[b * LAT + (LAT - 1)];

    float x[NN], y[NN];
    #pragma unroll
    for (int j = 0; j < NN; j++) {
        const float4 w = *reinterpret_cast<const float4*>(&s[K1_W1 + j * 4]);
        x[j] = fmaf(w.x, px, fmaf(w.y, py, fmaf(w.z, pz, w.w * cz)));
    }
    #pragma unroll
    for (int l = 0; l < NL; l++) {
        #pragma unroll
        for (int j = 0; j < NN; j++) {
            const float4* wr = reinterpret_cast<const float4*>(&s[K1_AW + l * 1024 + j * 32]);
            float a = s[K1_AB + l * 32 + j];
            #pragma unroll
            for (int i = 0; i < 8; i++) {
                const float4 w = wr[i];
                a = fmaf(w.x, x[4 * i + 0], a);
                a = fmaf(w.y, x[4 * i + 1], a);
                a = fmaf(w.z, x[4 * i + 2], a);
                a = fmaf(w.w, x[4 * i + 3], a);
            }
            y[j] = fmaxf(a, 0.0f) + x[j];
        }
        #pragma unroll
        for (int j = 0; j < NN; j++) x[j] = y[j];
    }
    float sacc = linamp2_b[0];
    #pragma unroll
    for (int i = 0; i < 8; i++) {
        const float4 w = *reinterpret_cast<const float4*>(&s[K1_W2 + i * 4]);
        sacc = fmaf(w.x, x[4 * i + 0], sacc);
        sacc = fmaf(w.y, x[4 * i + 1], sacc);
        sacc = fmaf(w.z, x[4 * i + 2], sacc);
        sacc = fmaf(w.w, x[4 * i + 3], sacc);
    }
    const float amp_corr = 1.0f / (1.0f + expf(-sacc));
    g_ampc[idx] = amp_corr;
    if (write_extras) out_ampc[idx] = amp_corr;
}

// ============ Kernel 2: deform head + project + splat ============
// smem: L0pad [384], DW [3072], DB [96], A1 [96], B1 [9], pad, KP [432]
#define K2_L0 0
#define K2_DW 384
#define K2_DB 3456
#define K2_A1 3552
#define K2_B1 3648
#define K2_KP 3660      // 3660*4 % 16 != 0 -> bump to 3664
#undef  K2_KP
#define K2_KP 3664
#define K2_TOT 4096

__global__ __launch_bounds__(128) void deform_splat_kernel(
    const float* __restrict__ z,          // [16,8]
    const float* __restrict__ r,          // [16,3,3]
    const float* __restrict__ pos,        // [20000,3]
    const float* __restrict__ amp,        // [1]
    const float* __restrict__ lin0_W,     // [32,10]
    const float* __restrict__ deform_W,   // [3,32,32]
    const float* __restrict__ deform_b,   // [3,32]
    const float* __restrict__ lin1a_W,    // [3,32]
    const float* __restrict__ lin1b_W,    // [3,3]
    const float* __restrict__ k2,         // [9,9]
    float* __restrict__ out_img,          // [16,256,256]
    float* __restrict__ out_posdef,       // [16,20000,3]
    float* __restrict__ out_res,          // [16,20000,3]
    int write_extras)
{
    __shared__ float s[K2_TOT];
    const int t = threadIdx.x;
    for (int i = t; i < 384; i += 128) {
        const int row = i / 12;
        const int c   = i - row * 12;
        s[K2_L0 + i] = (c < 10) ? lin0_W[row * 10 + c] : 0.0f;
    }
    for (int i = t; i < 3072; i += 128) s[K2_DW + i] = deform_W[i];
    for (int i = t; i < 96;   i += 128) s[K2_DB + i] = deform_b[i];
    for (int i = t; i < 96;   i += 128) s[K2_A1 + i] = lin1a_W[i];
    for (int i = t; i < 9;    i += 128) s[K2_B1 + i] = lin1b_W[i];
    for (int i = t; i < 432; i += 128) {
        const int o   = i / 108;
        const int rem = i - o * 108;
        const int row = rem / 12;
        const int m   = rem - row * 12;
        const int j   = m - o;
        s[K2_KP + i] = (j >= 0 && j < KS) ? k2[row * KS + j] : 0.0f;
    }
    __syncthreads();

    const int idx = blockIdx.x * 128 + t;
    if (idx >= NB * PNT) return;
    const int b = idx / PNT;
    const int p = idx - b * PNT;

    const float px = pos[p * 3 + 0];
    const float py = pos[p * 3 + 1];
    const float pz = pos[p * 3 + 2];

    float in10[12];
    in10[0] = px; in10[1] = py; in10[2] = pz;
    #pragma unroll
    for (int i = 0; i < LAT - 1; i++) in10[3 + i] = z[b * LAT + i];
    in10[10] = 0.0f; in10[11] = 0.0f;

    float x[NN], y[NN];
    #pragma unroll
    for (int j = 0; j < NN; j++) {
        const float4* wr = reinterpret_cast<const float4*>(&s[K2_L0 + j * 12]);
        float a = 0.0f;
        #pragma unroll
        for (int i = 0; i < 3; i++) {
            const float4 w = wr[i];
            a = fmaf(w.x, in10[4 * i + 0], a);
            a = fmaf(w.y, in10[4 * i + 1], a);
            a = fmaf(w.z, in10[4 * i + 2], a);
            a = fmaf(w.w, in10[4 * i + 3], a);
        }
        x[j] = a;
    }
    #pragma unroll
    for (int l = 0; l < NL; l++) {
        #pragma unroll
        for (int j = 0; j < NN; j++) {
            const float4* wr = reinterpret_cast<const float4*>(&s[K2_DW + l * 1024 + j * 32]);
            float a = s[K2_DB + l * 32 + j];
            #pragma unroll
            for (int i = 0; i < 8; i++) {
                const float4 w = wr[i];
                a = fmaf(w.x, x[4 * i + 0], a);
                a = fmaf(w.y, x[4 * i + 1], a);
                a = fmaf(w.z, x[4 * i + 2], a);
                a = fmaf(w.w, x[4 * i + 3], a);
            }
            y[j] = fmaxf(a, 0.0f) + x[j];
        }
        #pragma unroll
        for (int j = 0; j < NN; j++) x[j] = y[j];
    }
    float tv[3];
    #pragma unroll
    for (int k = 0; k < 3; k++) {
        const float4* wr = reinterpret_cast<const float4*>(&s[K2_A1 + k * 32]);
        float a = 0.0f;
        #pragma unroll
        for (int i = 0; i < 8; i++) {
            const float4 w = wr[i];
            a = fmaf(w.x, x[4 * i + 0], a);
            a = fmaf(w.y, x[4 * i + 1], a);
            a = fmaf(w.z, x[4 * i + 2], a);
            a = fmaf(w.w, x[4 * i + 3], a);
        }
        tv[k] = tanhf(a);
    }
    float resv[3];
    #pragma unroll
    for (int k = 0; k < 3; k++) {
        resv[k] = fmaf(s[K2_B1 + k * 3 + 0], tv[0],
                  fmaf(s[K2_B1 + k * 3 + 1], tv[1],
                       s[K2_B1 + k * 3 + 2] * tv[2]));
    }
    const float pdx = px + resv[0];
    const float pdy = py + resv[1];
    const float pdz = pz + resv[2];

    if (write_extras) {
        out_posdef[idx * 3 + 0] = pdx;
        out_posdef[idx * 3 + 1] = pdy;
        out_posdef[idx * 3 + 2] = pdz;
        out_res[idx * 3 + 0] = resv[0];
        out_res[idx * 3 + 1] = resv[1];
        out_res[idx * 3 + 2] = resv[2];
    }

    // ---------------- project + splat ----------------
    const float* rb = &r[b * 9];
    const float proj0 = fmaf(rb[0], pdx, fmaf(rb[1], pdy, rb[2] * pdz));
    const float proj1 = fmaf(rb[3], pdx, fmaf(rb[4], pdy, rb[5] * pdz));

    const float amps = amp[0] * g_ampc[idx];
    const int cx = __float2int_rn((proj0 + 0.5f) * (float)(BOX - 1));
    const int cy = __float2int_rn((proj1 + 0.5f) * (float)(BOX - 1));

    const int bx  = (cx - 4) & ~3;
    const int off = (cx - 4) - bx;
    const bool v0 = (bx >= 0) && (bx < BOX);
    const bool v1 = (bx + 4 >= 0) && (bx + 4 < BOX);
    const bool v2 = (bx + 8 >= 0) && (bx + 8 < BOX);
    const float* kp = &s[K2_KP + off * 108];

    float* img = out_img + (size_t)b * BOX * BOX;
    #pragma unroll
    for (int i = 0; i < KS; i++) {
        const int yy = cy + i - KS / 2;
        if ((unsigned)yy < (unsigned)BOX) {
            const float4 w0 = *reinterpret_cast<const float4*>(kp + i * 12 + 0);
            const float4 w1 = *reinterpret_cast<const float4*>(kp + i * 12 + 4);
            const float4 w2 = *reinterpret_cast<const float4*>(kp + i * 12 + 8);
            float* row = img + yy * BOX;
            if (v0) red_add_v4(row + bx,
                               amps * w0.x, amps * w0.y, amps * w0.z, amps * w0.w);
            if (v1) red_add_v4(row + bx + 4,
                               amps * w1.x, amps * w1.y, amps * w1.z, amps * w1.w);
            if (v2) red_add_v4(row + bx + 8,
                               amps * w2.x, amps * w2.y, amps * w2.z, amps * w2.w);
        }
    }
}

extern "C" void kernel_launch(void* const* d_in, const int* in_sizes, int n_in,
                              void* d_out, int out_size) {
    const float* z          = (const float*)d_in[0];
    const float* r          = (const float*)d_in[1];
    const float* pos        = (const float*)d_in[2];
    const float* amp        = (const float*)d_in[3];
    const float* linamp1_W  = (const float*)d_in[4];
    const float* ampblock_W = (const float*)d_in[5];
    const float* ampblock_b = (const float*)d_in[6];
    const float* linamp2_W  = (const float*)d_in[7];
    const float* linamp2_b  = (const float*)d_in[8];
    const float* lin0_W     = (const float*)d_in[9];
    const float* deform_W   = (const float*)d_in[10];
    const float* deform_b   = (const float*)d_in[11];
    const float* lin1a_W    = (const float*)d_in[12];
    const float* lin1b_W    = (const float*)d_in[13];
    const float* k2         = (const float*)d_in[14];
    // d_in[15] = d (always 1 for this problem)

    float* out = (float*)d_out;
    const long long IMG = (long long)NB * BOX * BOX;          // 1,048,576
    const long long PD  = (long long)NB * PNT * 3;            //   960,000
    const int write_extras = (out_size >= (int)(IMG + 2 * PD + (long long)NB * PNT)) ? 1 : 0;

    cudaMemsetAsync(out, 0, (size_t)IMG * sizeof(float));

    float* out_img    = out;
    float* out_posdef = out + IMG;
    float* out_res    = out + IMG + PD;
    float* out_ampc   = out + IMG + 2 * PD;

    const int total = NB * PNT;
    const int threads = 128;
    const int blocks = (total + threads - 1) / threads;

    amp_kernel<<<blocks, threads>>>(
        z, pos, linamp1_W, ampblock_W, ampblock_b, linamp2_W, linamp2_b,
        out_ampc, write_extras);

    deform_splat_kernel<<<blocks, threads>>>(
        z, r, pos, amp, lin0_W, deform_W, deform_b, lin1a_W, lin1b_W, k2,
        out_img, out_posdef, out_res, write_extras);
}